// round 2
// baseline (speedup 1.0000x reference)
#include <cuda_runtime.h>
#include <cuda_bf16.h>

// Scratch for segment start offsets. R = 250000 (+1 sentinel). __device__
// global => no allocation anywhere in kernel_launch.
#define MAX_R_PLUS_1 (1 << 22)
__device__ int g_seg_start[MAX_R_PLUS_1];

// Device-side dtype probe: under an int64 interpretation, the word at any odd
// position is a high word == 0 (values < 2^31). Under int32, the word at the
// largest odd position < N is a sorted index near R-1 (nonzero unless the
// whole array is zeros, which degenerates to identical results anyway).
__device__ __forceinline__ bool idx_is_i64(const int* i32, int N) {
    int j = (N - 1) | 1;        // largest odd index <= N-1
    if (j >= N) j -= 2;
    return i32[j] == 0;
}

__device__ __forceinline__ long long load_idx(const void* raw, int i, bool is64) {
    if (is64) return ((const long long*)raw)[i];
    return (long long)((const int*)raw)[i];
}

// Pass 1: boundaries of the sorted index. Residues in (idx[i-1], idx[i]]
// start at atom i. Thread N-1 closes the tail (empty trailing residues and
// the sentinel start[R] = N). All writes clamped to [0, R].
__global__ void rp_boundaries_kernel(const void* __restrict__ idx_raw,
                                     int N, int R, int* __restrict__ start) {
    int i = blockIdx.x * blockDim.x + threadIdx.x;
    if (i >= N) return;
    bool is64 = idx_is_i64((const int*)idx_raw, N);

    long long cur  = load_idx(idx_raw, i, is64);
    long long prev = (i == 0) ? -1LL : load_idx(idx_raw, i - 1, is64);

    long long lo = prev + 1; if (lo < 0) lo = 0;
    long long hi = cur;      if (hi > (long long)R) hi = (long long)R;
    for (long long r = lo; r <= hi; ++r) start[r] = i;

    if (i == N - 1) {
        long long lo2 = cur + 1; if (lo2 < 0) lo2 = 0;
        for (long long r = lo2; r <= (long long)R; ++r) start[r] = N;
    }
}

// Pass 2: one 128-thread block per residue, thread = feature column. Atom
// rows are contiguous, so each row is one fully coalesced 512B burst. Empty
// residues write zeros (count clamped to 1, matching the reference).
__global__ void rp_pool_kernel(const float* __restrict__ feat,
                               const int* __restrict__ start,
                               float* __restrict__ out, int D) {
    int r   = blockIdx.x;
    int tid = threadIdx.x;

    int s = __ldg(&start[r]);
    int e = __ldg(&start[r + 1]);

    // 4-way accumulators keep consecutive row LDGs independent (MLP up).
    float a0 = 0.f, a1 = 0.f, a2 = 0.f, a3 = 0.f;
    int a = s;
    for (; a + 3 < e; a += 4) {
        a0 += __ldg(&feat[(long long)(a + 0) * D + tid]);
        a1 += __ldg(&feat[(long long)(a + 1) * D + tid]);
        a2 += __ldg(&feat[(long long)(a + 2) * D + tid]);
        a3 += __ldg(&feat[(long long)(a + 3) * D + tid]);
    }
    for (; a < e; ++a) {
        a0 += __ldg(&feat[(long long)a * D + tid]);
    }
    float sum = (a0 + a1) + (a2 + a3);

    int cnt = e - s;
    float inv = 1.0f / (float)(cnt > 0 ? cnt : 1);
    out[(long long)r * D + tid] = sum * inv;
}

extern "C" void kernel_launch(void* const* d_in, const int* in_sizes, int n_in,
                              void* d_out, int out_size) {
    // Robust to input ordering: the feature tensor is the larger one.
    int fi = (in_sizes[0] >= in_sizes[1]) ? 0 : 1;
    int ii = 1 - fi;
    const float* feat    = (const float*)d_in[fi];
    const void*  idx_raw = d_in[ii];

    int N = in_sizes[ii];            // 2,000,000 atoms
    int D = in_sizes[fi] / N;        // 128
    int R = out_size / D;            // 250,000 residues
    float* out = (float*)d_out;

    int* start = nullptr;
    cudaGetSymbolAddress((void**)&start, g_seg_start);

    int threads = 256;
    int blocks  = (N + threads - 1) / threads;
    rp_boundaries_kernel<<<blocks, threads>>>(idx_raw, N, R, start);

    rp_pool_kernel<<<R, D>>>(feat, start, out, D);
}

// round 3
// speedup vs baseline: 1.7127x; 1.7127x over previous
#include <cuda_runtime.h>
#include <cuda_bf16.h>

// Scratch for segment start offsets. R = 250000 (+1 sentinel). __device__
// global => no allocation anywhere in kernel_launch.
#define MAX_R_PLUS_1 (1 << 22)
__device__ int g_seg_start[MAX_R_PLUS_1];

#define RPB 32   // residues per block in the pooling pass
#define UNR 8    // load batch depth (MLP per thread)

// Device-side dtype probe: under int64 the word at any odd position is a high
// word == 0; under int32 it is a sorted index near R-1 (nonzero).
__device__ __forceinline__ bool idx_is_i64(const int* i32, int N) {
    int j = (N - 1) | 1;
    if (j >= N) j -= 2;
    return i32[j] == 0;
}

__device__ __forceinline__ long long load_idx(const void* raw, int i, bool is64) {
    if (is64) return ((const long long*)raw)[i];
    return (long long)((const int*)raw)[i];
}

// Pass 1: boundaries of the sorted index. Residues in (idx[i-1], idx[i]]
// start at atom i; thread N-1 closes trailing empties + sentinel start[R]=N.
__global__ void rp_boundaries_kernel(const void* __restrict__ idx_raw,
                                     int N, int R, int* __restrict__ start) {
    int i = blockIdx.x * blockDim.x + threadIdx.x;
    if (i >= N) return;
    bool is64 = idx_is_i64((const int*)idx_raw, N);

    long long cur  = load_idx(idx_raw, i, is64);
    long long prev = (i == 0) ? -1LL : load_idx(idx_raw, i - 1, is64);

    long long lo = prev + 1; if (lo < 0) lo = 0;
    long long hi = cur;      if (hi > (long long)R) hi = (long long)R;
    for (long long r = lo; r <= hi; ++r) start[r] = i;

    if (i == N - 1) {
        long long lo2 = cur + 1; if (lo2 < 0) lo2 = 0;
        for (long long r = lo2; r <= (long long)R; ++r) start[r] = N;
    }
}

// Pass 2: one 128-thread block per RPB consecutive residues; thread = feature
// column. The block's residues cover one contiguous atom range, scanned as a
// single stream with UNR-deep independent load batches. Segment bookkeeping
// is uniform across the block (boundaries shared), so no divergence.
__global__ void rp_pool_kernel(const float* __restrict__ feat,
                               const int* __restrict__ start,
                               float* __restrict__ out, int D, int R) {
    __shared__ int ss[RPB + 1];

    int r0   = blockIdx.x * RPB;
    int nres = R - r0; if (nres > RPB) nres = RPB;
    int tid  = threadIdx.x;

    if (tid <= nres) ss[tid] = __ldg(&start[r0 + tid]);
    __syncthreads();

    const int A0 = ss[0];
    const int A1 = ss[nres];

    int   rloc = 0;
    int   e    = ss[1];
    float sum  = 0.f;

    for (int a = A0; a < A1; a += UNR) {
        float v[UNR];
#pragma unroll
        for (int k = 0; k < UNR; ++k) {
            int ai = a + k;
            v[k] = (ai < A1) ? __ldg(&feat[(size_t)ai * D + tid]) : 0.f;
        }
#pragma unroll
        for (int k = 0; k < UNR; ++k) {
            int ai = a + k;
            if (ai >= A1) break;
            while (ai >= e) {           // close segment(s), incl. empties
                int cnt = ss[rloc + 1] - ss[rloc];
                out[(size_t)(r0 + rloc) * D + tid] =
                    sum * (1.0f / (float)(cnt > 0 ? cnt : 1));
                sum = 0.f;
                ++rloc;
                e = ss[rloc + 1];       // rloc < nres guaranteed (ai < A1)
            }
            sum += v[k];
        }
    }

    // Flush the last open segment and any trailing empty residues.
    while (rloc < nres) {
        int cnt = ss[rloc + 1] - ss[rloc];
        out[(size_t)(r0 + rloc) * D + tid] =
            sum * (1.0f / (float)(cnt > 0 ? cnt : 1));
        sum = 0.f;
        ++rloc;
    }
}

extern "C" void kernel_launch(void* const* d_in, const int* in_sizes, int n_in,
                              void* d_out, int out_size) {
    int fi = (in_sizes[0] >= in_sizes[1]) ? 0 : 1;
    int ii = 1 - fi;
    const float* feat    = (const float*)d_in[fi];
    const void*  idx_raw = d_in[ii];

    int N = in_sizes[ii];            // 2,000,000 atoms
    int D = in_sizes[fi] / N;        // 128
    int R = out_size / D;            // 250,000 residues
    float* out = (float*)d_out;

    int* start = nullptr;
    cudaGetSymbolAddress((void**)&start, g_seg_start);

    int threads = 256;
    int blocks  = (N + threads - 1) / threads;
    rp_boundaries_kernel<<<blocks, threads>>>(idx_raw, N, R, start);

    int pool_blocks = (R + RPB - 1) / RPB;
    rp_pool_kernel<<<pool_blocks, D>>>(feat, start, out, D, R);
}

// round 4
// speedup vs baseline: 1.8825x; 1.0992x over previous
#include <cuda_runtime.h>
#include <cuda_bf16.h>

// Scratch for segment start offsets. R = 250000 (+1 sentinel). __device__
// global => no allocation anywhere in kernel_launch.
#define MAX_R_PLUS_1 (1 << 22)
__device__ int g_seg_start[MAX_R_PLUS_1];

#define RPW 16   // residues per warp in the pooling pass (boundaries fit lanes)
#define UNR 4    // float4 load batch depth (64B per thread in flight)

// Device-side dtype probe: under int64 the word at any odd position is a high
// word == 0; under int32 it is a sorted index near R-1 (nonzero).
__device__ __forceinline__ bool idx_is_i64(const int* i32, int N) {
    int j = (N - 1) | 1;
    if (j >= N) j -= 2;
    return i32[j] == 0;
}

__device__ __forceinline__ long long load_idx(const void* raw, int i, bool is64) {
    if (is64) return ((const long long*)raw)[i];
    return (long long)((const int*)raw)[i];
}

// Pass 1: boundaries of the sorted index. Residues in (idx[i-1], idx[i]]
// start at atom i; thread N-1 closes trailing empties + sentinel start[R]=N.
__global__ void rp_boundaries_kernel(const void* __restrict__ idx_raw,
                                     int N, int R, int* __restrict__ start) {
    int i = blockIdx.x * blockDim.x + threadIdx.x;
    if (i >= N) return;
    bool is64 = idx_is_i64((const int*)idx_raw, N);

    long long cur  = load_idx(idx_raw, i, is64);
    long long prev = (i == 0) ? -1LL : load_idx(idx_raw, i - 1, is64);

    long long lo = prev + 1; if (lo < 0) lo = 0;
    long long hi = cur;      if (hi > (long long)R) hi = (long long)R;
    for (long long r = lo; r <= hi; ++r) start[r] = i;

    if (i == N - 1) {
        long long lo2 = cur + 1; if (lo2 < 0) lo2 = 0;
        for (long long r = lo2; r <= (long long)R; ++r) start[r] = N;
    }
}

// Pass 2: one WARP per RPW consecutive residues. Lane = float4 column group
// (D/4 = 32 lanes per row). Each warp streams its contiguous atom range with
// UNR-deep wide loads; segment boundaries are held in lane registers and
// fetched via shuffle, so bookkeeping is register-only and warp-uniform.
__global__ void rp_pool_kernel(const float4* __restrict__ feat4,
                               const int* __restrict__ start,
                               float4* __restrict__ out4, int R) {
    const unsigned FULL = 0xffffffffu;
    int gwarp = (blockIdx.x * blockDim.x + threadIdx.x) >> 5;
    int lane  = threadIdx.x & 31;

    int r0 = gwarp * RPW;
    if (r0 >= R) return;
    int nres = R - r0; if (nres > RPW) nres = RPW;

    // Lane l holds boundary start[r0 + min(l, nres)]; boundary(i) = shfl(b, i).
    int b = __ldg(&start[r0 + (lane < nres ? lane : nres)]);

    const int A0 = __shfl_sync(FULL, b, 0);
    const int A1 = __shfl_sync(FULL, b, nres);

    int    rloc   = 0;
    int    sstart = A0;
    int    e      = __shfl_sync(FULL, b, (nres >= 1) ? 1 : 0);
    float4 sum    = make_float4(0.f, 0.f, 0.f, 0.f);

    for (int a = A0; a < A1; a += UNR) {
        float4 v[UNR];
#pragma unroll
        for (int k = 0; k < UNR; ++k) {
            int ai = a + k;
            v[k] = (ai < A1) ? __ldg(&feat4[(size_t)ai * 32 + lane])
                             : make_float4(0.f, 0.f, 0.f, 0.f);
        }
#pragma unroll
        for (int k = 0; k < UNR; ++k) {
            int ai = a + k;
            if (ai >= A1) break;
            while (ai >= e) {               // close segment(s), incl. empties
                int   cnt = e - sstart;
                float inv = 1.0f / (float)(cnt > 0 ? cnt : 1);
                float4 o = make_float4(sum.x * inv, sum.y * inv,
                                       sum.z * inv, sum.w * inv);
                out4[(size_t)(r0 + rloc) * 32 + lane] = o;
                sum = make_float4(0.f, 0.f, 0.f, 0.f);
                sstart = e;
                ++rloc;                     // rloc < nres guaranteed (ai < A1)
                e = __shfl_sync(FULL, b, rloc + 1);
            }
            sum.x += v[k].x; sum.y += v[k].y;
            sum.z += v[k].z; sum.w += v[k].w;
        }
    }

    // Flush the last open segment and trailing empty residues.
    while (rloc < nres) {
        int   cnt = e - sstart;
        float inv = 1.0f / (float)(cnt > 0 ? cnt : 1);
        float4 o = make_float4(sum.x * inv, sum.y * inv,
                               sum.z * inv, sum.w * inv);
        out4[(size_t)(r0 + rloc) * 32 + lane] = o;
        sum = make_float4(0.f, 0.f, 0.f, 0.f);
        sstart = e;
        ++rloc;
        if (rloc < nres) e = __shfl_sync(FULL, b, rloc + 1);
    }
}

extern "C" void kernel_launch(void* const* d_in, const int* in_sizes, int n_in,
                              void* d_out, int out_size) {
    int fi = (in_sizes[0] >= in_sizes[1]) ? 0 : 1;
    int ii = 1 - fi;
    const float* feat    = (const float*)d_in[fi];
    const void*  idx_raw = d_in[ii];

    int N = in_sizes[ii];            // 2,000,000 atoms
    int D = in_sizes[fi] / N;        // 128
    int R = out_size / D;            // 250,000 residues
    float* out = (float*)d_out;

    int* start = nullptr;
    cudaGetSymbolAddress((void**)&start, g_seg_start);

    int threads = 256;
    int blocks  = (N + threads - 1) / threads;
    rp_boundaries_kernel<<<blocks, threads>>>(idx_raw, N, R, start);

    int nwarps      = (R + RPW - 1) / RPW;
    int pool_blocks = (nwarps * 32 + threads - 1) / threads;
    rp_pool_kernel<<<pool_blocks, threads>>>((const float4*)feat, start,
                                             (float4*)out, R);
}

// round 6
// speedup vs baseline: 1.9060x; 1.0125x over previous
#include <cuda_runtime.h>
#include <cuda_bf16.h>

// Scratch for segment start offsets. R = 250000 (+1 sentinel). __device__
// global => no allocation anywhere in kernel_launch.
#define MAX_R_PLUS_1 (1 << 22)
__device__ int g_seg_start[MAX_R_PLUS_1];

#define RPW 8    // residues per warp (boundaries live in lanes 0..RPW)
#define UNR 4    // float4 load batch depth (64B per thread in flight)

// Device-side dtype probe: under int64 the word at any odd position is a high
// word == 0; under int32 it is a sorted index near R-1 (nonzero).
__device__ __forceinline__ bool idx_is_i64(const int* i32, int N) {
    int j = (N - 1) | 1;
    if (j >= N) j -= 2;
    return i32[j] == 0;
}

__device__ __forceinline__ long long load_idx(const void* raw, int i, bool is64) {
    if (is64) return ((const long long*)raw)[i];
    return (long long)((const int*)raw)[i];
}

// Pass 1: boundaries of the sorted index. Each thread loads idx[i] ONCE;
// prev comes from the lane below via shuffle (lane 0 re-loads idx[i-1]).
// Residues in (prev, cur] start at atom i; thread N-1 closes trailing
// empties + sentinel start[R] = N.
__global__ void rp_boundaries_kernel(const void* __restrict__ idx_raw,
                                     int N, int R, int* __restrict__ start) {
    const unsigned FULL = 0xffffffffu;
    int i    = blockIdx.x * blockDim.x + threadIdx.x;
    int lane = threadIdx.x & 31;
    bool is64 = idx_is_i64((const int*)idx_raw, N);

    long long cur  = (i < N) ? load_idx(idx_raw, i, is64) : 0;
    long long prev = __shfl_up_sync(FULL, cur, 1);
    if (lane == 0) prev = (i == 0) ? -1LL
                                   : ((i <= N) ? load_idx(idx_raw, i - 1, is64) : 0);
    if (i >= N) return;

    long long lo = prev + 1; if (lo < 0) lo = 0;
    long long hi = cur;      if (hi > (long long)R) hi = (long long)R;
    for (long long r = lo; r <= hi; ++r) start[r] = i;

    if (i == N - 1) {
        long long lo2 = cur + 1; if (lo2 < 0) lo2 = 0;
        for (long long r = lo2; r <= (long long)R; ++r) start[r] = N;
    }
}

// Pass 2: one WARP per RPW consecutive residues. Lane = float4 column group
// (D/4 = 32 lanes per row). Each warp streams its contiguous atom range with
// UNR-deep wide loads; boundaries live in lane registers via shuffle.
__global__ void __launch_bounds__(256, 6)
rp_pool_kernel(const float4* __restrict__ feat4,
               const int* __restrict__ start,
               float4* __restrict__ out4, int R) {
    const unsigned FULL = 0xffffffffu;
    int gwarp = (blockIdx.x * blockDim.x + threadIdx.x) >> 5;
    int lane  = threadIdx.x & 31;

    int r0 = gwarp * RPW;
    if (r0 >= R) return;
    int nres = R - r0; if (nres > RPW) nres = RPW;

    // Lane l holds boundary start[r0 + min(l, nres)]; boundary(i) = shfl(b, i).
    int b = __ldg(&start[r0 + (lane < nres ? lane : nres)]);

    const int A0 = __shfl_sync(FULL, b, 0);
    const int A1 = __shfl_sync(FULL, b, nres);

    int    rloc   = 0;
    int    sstart = A0;
    int    e      = __shfl_sync(FULL, b, (nres >= 1) ? 1 : 0);
    float4 sum    = make_float4(0.f, 0.f, 0.f, 0.f);

    for (int a = A0; a < A1; a += UNR) {
        float4 v[UNR];
#pragma unroll
        for (int k = 0; k < UNR; ++k) {
            int ai = a + k;
            v[k] = (ai < A1) ? __ldg(&feat4[(size_t)ai * 32 + lane])
                             : make_float4(0.f, 0.f, 0.f, 0.f);
        }
#pragma unroll
        for (int k = 0; k < UNR; ++k) {
            int ai = a + k;
            if (ai >= A1) break;
            while (ai >= e) {               // close segment(s), incl. empties
                int   cnt = e - sstart;
                float inv = 1.0f / (float)(cnt > 0 ? cnt : 1);
                out4[(size_t)(r0 + rloc) * 32 + lane] =
                    make_float4(sum.x * inv, sum.y * inv,
                                sum.z * inv, sum.w * inv);
                sum = make_float4(0.f, 0.f, 0.f, 0.f);
                sstart = e;
                ++rloc;                     // rloc < nres guaranteed (ai < A1)
                e = __shfl_sync(FULL, b, rloc + 1);
            }
            sum.x += v[k].x; sum.y += v[k].y;
            sum.z += v[k].z; sum.w += v[k].w;
        }
    }

    // Flush the last open segment and trailing empty residues.
    while (rloc < nres) {
        int   cnt = e - sstart;
        float inv = 1.0f / (float)(cnt > 0 ? cnt : 1);
        out4[(size_t)(r0 + rloc) * 32 + lane] =
            make_float4(sum.x * inv, sum.y * inv, sum.z * inv, sum.w * inv);
        sum = make_float4(0.f, 0.f, 0.f, 0.f);
        sstart = e;
        ++rloc;
        if (rloc < nres) e = __shfl_sync(FULL, b, rloc + 1);
    }
}

extern "C" void kernel_launch(void* const* d_in, const int* in_sizes, int n_in,
                              void* d_out, int out_size) {
    int fi = (in_sizes[0] >= in_sizes[1]) ? 0 : 1;
    int ii = 1 - fi;
    const float* feat    = (const float*)d_in[fi];
    const void*  idx_raw = d_in[ii];

    int N = in_sizes[ii];            // 2,000,000 atoms
    int D = in_sizes[fi] / N;        // 128
    int R = out_size / D;            // 250,000 residues
    float* out = (float*)d_out;

    int* start = nullptr;
    cudaGetSymbolAddress((void**)&start, g_seg_start);

    int threads = 256;
    int blocks  = (N + threads - 1) / threads;
    rp_boundaries_kernel<<<blocks, threads>>>(idx_raw, N, R, start);

    int nwarps      = (R + RPW - 1) / RPW;
    int pool_blocks = (nwarps * 32 + threads - 1) / threads;
    rp_pool_kernel<<<pool_blocks, threads>>>((const float4*)feat, start,
                                             (float4*)out, R);
}